// round 1
// baseline (speedup 1.0000x reference)
#include <cuda_runtime.h>
#include <cuda_bf16.h>
#include <math.h>

// Problem dims (fixed per reference)
#define NTOK 4096
#define DMODEL 1024

// Scratch (no cudaMalloc allowed)
__device__ float g_Q[NTOK * DMODEL];
__device__ float g_K[NTOK * DMODEL];
__device__ float g_V[NTOK * DMODEL];
__device__ float g_S[(size_t)NTOK * NTOK];

// ---------------------------------------------------------------------------
// Tiled SGEMM: C[M,N] = alpha * A[M,K] @ op(B) (+ bias)
//   TRANSB=false: B is [K,N] row-major (NN)
//   TRANSB=true:  B is [N,K] row-major, use B^T (NT)
// BM=BN=128, BK=8, 256 threads, 8x8 per-thread microtile.
// Requires M%128==0, N%128==0, K%8==0 (true for all our shapes).
// ---------------------------------------------------------------------------
template <bool TRANSB, bool HAS_BIAS>
__global__ __launch_bounds__(256, 2)
void sgemm_kernel(const float* __restrict__ A,
                  const float* __restrict__ B,
                  const float* __restrict__ bias,
                  float* __restrict__ C,
                  int M, int N, int K, float alpha)
{
    __shared__ float As[8][132];
    __shared__ float Bs[8][132];

    const int tid = threadIdx.x;
    const int tx = tid & 15;         // 0..15  -> col group
    const int ty = tid >> 4;         // 0..15  -> row group
    const int bm = blockIdx.y * 128;
    const int bn = blockIdx.x * 128;

    float acc[8][8];
#pragma unroll
    for (int i = 0; i < 8; i++)
#pragma unroll
        for (int j = 0; j < 8; j++) acc[i][j] = 0.0f;

    // A-tile load mapping: 128 rows x 8 cols = 256 float4
    const int a_m  = tid >> 1;          // 0..127
    const int a_k4 = (tid & 1) * 4;     // 0 or 4

    // B-tile load mapping (NN): 8 rows x 128 cols = 256 float4
    const int b_k  = tid >> 5;          // 0..7
    const int b_n4 = (tid & 31) * 4;    // 0..124

    for (int k0 = 0; k0 < K; k0 += 8) {
        // load A tile (transposed into As[kk][m])
        {
            float4 v = *reinterpret_cast<const float4*>(
                A + (size_t)(bm + a_m) * K + k0 + a_k4);
            As[a_k4 + 0][a_m] = v.x;
            As[a_k4 + 1][a_m] = v.y;
            As[a_k4 + 2][a_m] = v.z;
            As[a_k4 + 3][a_m] = v.w;
        }
        // load B tile
        if (TRANSB) {
            // B is [N,K]; Bs[kk][n] = B[bn+n][k0+kk]
            float4 v = *reinterpret_cast<const float4*>(
                B + (size_t)(bn + a_m) * K + k0 + a_k4);
            Bs[a_k4 + 0][a_m] = v.x;
            Bs[a_k4 + 1][a_m] = v.y;
            Bs[a_k4 + 2][a_m] = v.z;
            Bs[a_k4 + 3][a_m] = v.w;
        } else {
            // B is [K,N]; Bs[kk][n] = B[k0+kk][bn+n]
            float4 v = *reinterpret_cast<const float4*>(
                B + (size_t)(k0 + b_k) * N + bn + b_n4);
            Bs[b_k][b_n4 + 0] = v.x;
            Bs[b_k][b_n4 + 1] = v.y;
            Bs[b_k][b_n4 + 2] = v.z;
            Bs[b_k][b_n4 + 3] = v.w;
        }
        __syncthreads();

#pragma unroll
        for (int kk = 0; kk < 8; kk++) {
            float a[8], b[8];
#pragma unroll
            for (int i = 0; i < 8; i++) a[i] = As[kk][ty * 8 + i];
#pragma unroll
            for (int j = 0; j < 8; j++) b[j] = Bs[kk][tx * 8 + j];
#pragma unroll
            for (int i = 0; i < 8; i++)
#pragma unroll
                for (int j = 0; j < 8; j++)
                    acc[i][j] = fmaf(a[i], b[j], acc[i][j]);
        }
        __syncthreads();
    }

    // epilogue
#pragma unroll
    for (int i = 0; i < 8; i++) {
        const int row = bm + ty * 8 + i;
        float* crow = C + (size_t)row * N + bn + tx * 8;
#pragma unroll
        for (int j4 = 0; j4 < 8; j4 += 4) {
            float4 v;
            v.x = acc[i][j4 + 0] * alpha;
            v.y = acc[i][j4 + 1] * alpha;
            v.z = acc[i][j4 + 2] * alpha;
            v.w = acc[i][j4 + 3] * alpha;
            if (HAS_BIAS) {
                const float* bp = bias + bn + tx * 8 + j4;
                v.x += bp[0]; v.y += bp[1]; v.z += bp[2]; v.w += bp[3];
            }
            *reinterpret_cast<float4*>(crow + j4) = v;
        }
    }
}

// ---------------------------------------------------------------------------
// Row softmax, in place. One block (256 threads) per row of length N.
// ---------------------------------------------------------------------------
__global__ __launch_bounds__(256)
void softmax_rows_kernel(float* __restrict__ S, int N)
{
    __shared__ float red[256];
    const int tid = threadIdx.x;
    float* p = S + (size_t)blockIdx.x * N;

    // max
    float m = -INFINITY;
    for (int i = tid; i < N; i += 256) m = fmaxf(m, p[i]);
    red[tid] = m;
    __syncthreads();
    for (int s = 128; s > 0; s >>= 1) {
        if (tid < s) red[tid] = fmaxf(red[tid], red[tid + s]);
        __syncthreads();
    }
    m = red[0];
    __syncthreads();

    // exp + sum
    float sum = 0.0f;
    for (int i = tid; i < N; i += 256) {
        float e = __expf(p[i] - m);
        p[i] = e;
        sum += e;
    }
    red[tid] = sum;
    __syncthreads();
    for (int s = 128; s > 0; s >>= 1) {
        if (tid < s) red[tid] += red[tid + s];
        __syncthreads();
    }
    const float inv = 1.0f / red[0];
    __syncthreads();

    for (int i = tid; i < N; i += 256) p[i] *= inv;
}

// ---------------------------------------------------------------------------
extern "C" void kernel_launch(void* const* d_in, const int* in_sizes, int n_in,
                              void* d_out, int out_size)
{
    const float* x  = (const float*)d_in[0];
    const float* Wq = (const float*)d_in[1];
    const float* Wk = (const float*)d_in[2];
    const float* Wv = (const float*)d_in[3];
    const float* bq = (const float*)d_in[4];
    const float* bk = (const float*)d_in[5];
    const float* bv = (const float*)d_in[6];
    float* out = (float*)d_out;

    float *Q, *K, *V, *S;
    cudaGetSymbolAddress((void**)&Q, g_Q);
    cudaGetSymbolAddress((void**)&K, g_K);
    cudaGetSymbolAddress((void**)&V, g_V);
    cudaGetSymbolAddress((void**)&S, g_S);

    const int M = NTOK, D = DMODEL;
    dim3 threads(256);

    // QKV projections: [4096,1024] = [4096,1024] @ [1024,1024] + bias
    {
        dim3 grid(D / 128, M / 128);
        sgemm_kernel<false, true><<<grid, threads>>>(x, Wq, bq, Q, M, D, D, 1.0f);
        sgemm_kernel<false, true><<<grid, threads>>>(x, Wk, bk, K, M, D, D, 1.0f);
        sgemm_kernel<false, true><<<grid, threads>>>(x, Wv, bv, V, M, D, D, 1.0f);
    }

    // S = (1/sqrt(d)) * Q @ K^T   [4096,4096]
    {
        dim3 grid(M / 128, M / 128);
        const float scale = 1.0f / 32.0f;  // 1/sqrt(1024)
        sgemm_kernel<true, false><<<grid, threads>>>(Q, K, nullptr, S, M, M, D, scale);
    }

    // softmax rows, in place
    softmax_rows_kernel<<<M, threads>>>(S, M);

    // out = P @ V   [4096,1024]
    {
        dim3 grid(D / 128, M / 128);
        sgemm_kernel<false, false><<<grid, threads>>>(S, V, nullptr, out, M, D, M, 1.0f);
    }
}

// round 2
// speedup vs baseline: 3.2679x; 3.2679x over previous
#include <cuda_runtime.h>
#include <cuda_bf16.h>
#include <math.h>
#include <stdint.h>

#define NTOK 4096
#define DMODEL 1024

// Scratch (no cudaMalloc allowed)
__device__ float g_Q[NTOK * DMODEL];
__device__ float g_K[NTOK * DMODEL];
__device__ float g_V[NTOK * DMODEL];
__device__ float g_S[(size_t)NTOK * NTOK];
__device__ float g_Xc[NTOK * DMODEL];           // tf32-rounded x
__device__ float g_Wc[3 * DMODEL * DMODEL];     // tf32-rounded Wq|Wk|Wv

// ---------------------------------------------------------------------------
__device__ __forceinline__ float cvt_rna_tf32(float v) {
    uint32_t o;
    asm("cvt.rna.tf32.f32 %0, %1;" : "=r"(o) : "f"(v));
    return __uint_as_float(o);
}

__device__ __forceinline__ void mma_tf32(float (&d)[4], const uint32_t (&a)[4],
                                         const uint32_t (&b)[2]) {
    asm volatile(
        "mma.sync.aligned.m16n8k8.row.col.f32.tf32.tf32.f32 "
        "{%0,%1,%2,%3}, {%4,%5,%6,%7}, {%8,%9}, {%0,%1,%2,%3};"
        : "+f"(d[0]), "+f"(d[1]), "+f"(d[2]), "+f"(d[3])
        : "r"(a[0]), "r"(a[1]), "r"(a[2]), "r"(a[3]), "r"(b[0]), "r"(b[1]));
}

__device__ __forceinline__ void cp_async16(uint32_t smem_addr, const void* gptr) {
    asm volatile("cp.async.cg.shared.global [%0], [%1], 16;\n"
                 :: "r"(smem_addr), "l"(gptr));
}
__device__ __forceinline__ void cp_commit() {
    asm volatile("cp.async.commit_group;\n");
}
template <int N>
__device__ __forceinline__ void cp_wait() {
    asm volatile("cp.async.wait_group %0;\n" :: "n"(N));
}

// ---------------------------------------------------------------------------
// tf32 tensor-core GEMM: C[M,N] = alpha * A[M,K] @ op(B) (+bias) (optional rna)
//   TRANSB=0: B is [K,N] row-major.  TRANSB=1: B is [N,K] row-major (use B^T).
// Inputs A,B must already be tf32-valued fp32. 128 threads, BM=BN=128, BK=32,
// 4 warps each computing a 64x64 warp tile via m16n8k8 MMAs.
// ---------------------------------------------------------------------------
#define ASTRIDE 36
#define BSTRIDE_NN 136
#define A_WORDS (128 * ASTRIDE)          // 4608
#define B_WORDS_NT (128 * ASTRIDE)       // 4608
#define B_WORDS_NN (32 * BSTRIDE_NN)     // 4352

template <bool TRANSB, bool HAS_BIAS, bool ROUND_OUT>
__global__ __launch_bounds__(128)
void tc_gemm(const float* __restrict__ A, const float* __restrict__ B,
             const float* __restrict__ bias, float* __restrict__ C,
             int M, int N, int K, float alpha)
{
    extern __shared__ float sm[];
    constexpr int BWORDS = TRANSB ? B_WORDS_NT : B_WORDS_NN;
    float* As[2] = { sm, sm + A_WORDS };
    float* Bs[2] = { sm + 2 * A_WORDS, sm + 2 * A_WORDS + BWORDS };

    const int tid  = threadIdx.x;
    const int lane = tid & 31;
    const int warp = tid >> 5;
    const int wm = (warp >> 1) * 64;      // warp tile row origin in CTA
    const int wn = (warp & 1) * 64;       // warp tile col origin
    const int r_ = lane >> 2;             // 0..7
    const int c_ = lane & 3;              // 0..3
    const int bm = blockIdx.y * 128;
    const int bn = blockIdx.x * 128;

    float acc[4][8][4];
#pragma unroll
    for (int i = 0; i < 4; i++)
#pragma unroll
        for (int j = 0; j < 8; j++)
#pragma unroll
            for (int v = 0; v < 4; v++) acc[i][j][v] = 0.0f;

    // per-thread load geometry (8 x 16B for A, 8 x 16B for B)
    // A tile: 128(m) x 32(k);  id = i*128+tid: m=id>>3, k4=(id&7)*4
    // B NN  : 32(k) x 128(n);  k=id>>5, n4=(id&31)*4
    // B NT  : 128(n) x 32(k);  n=id>>3, k4=(id&7)*4
    uint32_t smbaseA[2], smbaseB[2];
    smbaseA[0] = (uint32_t)__cvta_generic_to_shared(As[0]);
    smbaseA[1] = (uint32_t)__cvta_generic_to_shared(As[1]);
    smbaseB[0] = (uint32_t)__cvta_generic_to_shared(Bs[0]);
    smbaseB[1] = (uint32_t)__cvta_generic_to_shared(Bs[1]);

    const int nch = K / 32;

    auto issue = [&](int chunk, int buf) {
        const int k0 = chunk * 32;
#pragma unroll
        for (int i = 0; i < 8; i++) {
            int id = i * 128 + tid;
            int am = id >> 3, ak4 = (id & 7) * 4;
            cp_async16(smbaseA[buf] + 4u * (am * ASTRIDE + ak4),
                       A + (size_t)(bm + am) * K + k0 + ak4);
        }
        if (TRANSB) {
#pragma unroll
            for (int i = 0; i < 8; i++) {
                int id = i * 128 + tid;
                int bnr = id >> 3, bk4 = (id & 7) * 4;
                cp_async16(smbaseB[buf] + 4u * (bnr * ASTRIDE + bk4),
                           B + (size_t)(bn + bnr) * K + k0 + bk4);
            }
        } else {
#pragma unroll
            for (int i = 0; i < 8; i++) {
                int id = i * 128 + tid;
                int bk = id >> 5, bn4 = (id & 31) * 4;
                cp_async16(smbaseB[buf] + 4u * (bk * BSTRIDE_NN + bn4),
                           B + (size_t)(k0 + bk) * N + bn + bn4);
            }
        }
        cp_commit();
    };

    issue(0, 0);

    for (int c = 0; c < nch; c++) {
        const int cur = c & 1;
        if (c + 1 < nch) {
            issue(c + 1, cur ^ 1);
            cp_wait<1>();
        } else {
            cp_wait<0>();
        }
        __syncthreads();

        const float* __restrict__ Acur = As[cur];
        const float* __restrict__ Bcur = Bs[cur];

#pragma unroll
        for (int ks = 0; ks < 4; ks++) {
            uint32_t afr[4][4];
#pragma unroll
            for (int mt = 0; mt < 4; mt++) {
                int row = wm + mt * 16 + r_;
                afr[mt][0] = __float_as_uint(Acur[row * ASTRIDE + ks * 8 + c_]);
                afr[mt][1] = __float_as_uint(Acur[(row + 8) * ASTRIDE + ks * 8 + c_]);
                afr[mt][2] = __float_as_uint(Acur[row * ASTRIDE + ks * 8 + c_ + 4]);
                afr[mt][3] = __float_as_uint(Acur[(row + 8) * ASTRIDE + ks * 8 + c_ + 4]);
            }
            uint32_t bfr[8][2];
#pragma unroll
            for (int nt = 0; nt < 8; nt++) {
                int col = wn + nt * 8 + r_;   // r_ = lane>>2 is the n index
                if (TRANSB) {
                    bfr[nt][0] = __float_as_uint(Bcur[col * ASTRIDE + ks * 8 + c_]);
                    bfr[nt][1] = __float_as_uint(Bcur[col * ASTRIDE + ks * 8 + c_ + 4]);
                } else {
                    bfr[nt][0] = __float_as_uint(Bcur[(ks * 8 + c_) * BSTRIDE_NN + col]);
                    bfr[nt][1] = __float_as_uint(Bcur[(ks * 8 + c_ + 4) * BSTRIDE_NN + col]);
                }
            }
#pragma unroll
            for (int mt = 0; mt < 4; mt++)
#pragma unroll
                for (int nt = 0; nt < 8; nt++)
                    mma_tf32(acc[mt][nt], afr[mt], bfr[nt]);
        }
        __syncthreads();
    }

    // epilogue: acc layout per thread: rows (lane>>2, +8), cols 2*(lane&3), +1
#pragma unroll
    for (int mt = 0; mt < 4; mt++) {
#pragma unroll
        for (int nt = 0; nt < 8; nt++) {
            int row0 = bm + wm + mt * 16 + r_;
            int col  = bn + wn + nt * 8 + 2 * c_;
            float v0 = acc[mt][nt][0] * alpha;
            float v1 = acc[mt][nt][1] * alpha;
            float v2 = acc[mt][nt][2] * alpha;
            float v3 = acc[mt][nt][3] * alpha;
            if (HAS_BIAS) {
                float b0 = bias[col], b1 = bias[col + 1];
                v0 += b0; v1 += b1; v2 += b0; v3 += b1;
            }
            if (ROUND_OUT) {
                v0 = cvt_rna_tf32(v0); v1 = cvt_rna_tf32(v1);
                v2 = cvt_rna_tf32(v2); v3 = cvt_rna_tf32(v3);
            }
            float2 lo = make_float2(v0, v1);
            float2 hi = make_float2(v2, v3);
            *reinterpret_cast<float2*>(C + (size_t)row0 * N + col) = lo;
            *reinterpret_cast<float2*>(C + (size_t)(row0 + 8) * N + col) = hi;
        }
    }
}

// ---------------------------------------------------------------------------
// tf32 pre-rounding (elementwise, float4)
// ---------------------------------------------------------------------------
__global__ __launch_bounds__(256)
void cvt_tf32_kernel(const float* __restrict__ in, float* __restrict__ out, int n4)
{
    int i = blockIdx.x * 256 + threadIdx.x;
    int stride = gridDim.x * 256;
    for (; i < n4; i += stride) {
        float4 v = reinterpret_cast<const float4*>(in)[i];
        v.x = cvt_rna_tf32(v.x); v.y = cvt_rna_tf32(v.y);
        v.z = cvt_rna_tf32(v.z); v.w = cvt_rna_tf32(v.w);
        reinterpret_cast<float4*>(out)[i] = v;
    }
}

// ---------------------------------------------------------------------------
// Row softmax in place; final probs rounded to tf32 for the P@V GEMM.
// ---------------------------------------------------------------------------
__global__ __launch_bounds__(256)
void softmax_rows_kernel(float* __restrict__ S, int N)
{
    __shared__ float red[256];
    const int tid = threadIdx.x;
    float* p = S + (size_t)blockIdx.x * N;

    float m = -INFINITY;
    for (int i = tid; i < N; i += 256) m = fmaxf(m, p[i]);
    red[tid] = m;
    __syncthreads();
    for (int s = 128; s > 0; s >>= 1) {
        if (tid < s) red[tid] = fmaxf(red[tid], red[tid + s]);
        __syncthreads();
    }
    m = red[0];
    __syncthreads();

    float sum = 0.0f;
    for (int i = tid; i < N; i += 256) {
        float e = __expf(p[i] - m);
        p[i] = e;
        sum += e;
    }
    red[tid] = sum;
    __syncthreads();
    for (int s = 128; s > 0; s >>= 1) {
        if (tid < s) red[tid] += red[tid + s];
        __syncthreads();
    }
    const float inv = 1.0f / red[0];
    __syncthreads();

    for (int i = tid; i < N; i += 256) p[i] = cvt_rna_tf32(p[i] * inv);
}

// ---------------------------------------------------------------------------
extern "C" void kernel_launch(void* const* d_in, const int* in_sizes, int n_in,
                              void* d_out, int out_size)
{
    const float* x  = (const float*)d_in[0];
    const float* Wq = (const float*)d_in[1];
    const float* Wk = (const float*)d_in[2];
    const float* Wv = (const float*)d_in[3];
    const float* bq = (const float*)d_in[4];
    const float* bk = (const float*)d_in[5];
    const float* bv = (const float*)d_in[6];
    float* out = (float*)d_out;

    float *Q, *K, *V, *S, *Xc, *Wc;
    cudaGetSymbolAddress((void**)&Q,  g_Q);
    cudaGetSymbolAddress((void**)&K,  g_K);
    cudaGetSymbolAddress((void**)&V,  g_V);
    cudaGetSymbolAddress((void**)&S,  g_S);
    cudaGetSymbolAddress((void**)&Xc, g_Xc);
    cudaGetSymbolAddress((void**)&Wc, g_Wc);

    const int M = NTOK, D = DMODEL;

    // raise dynamic smem limits (idempotent, graph-capture safe)
    constexpr int SMEM_NT = (2 * A_WORDS + 2 * B_WORDS_NT) * 4;   // 73728
    constexpr int SMEM_NN = (2 * A_WORDS + 2 * B_WORDS_NN) * 4;   // 71680
    cudaFuncSetAttribute(tc_gemm<false, true,  true>,
                         cudaFuncAttributeMaxDynamicSharedMemorySize, SMEM_NN);
    cudaFuncSetAttribute(tc_gemm<true,  false, false>,
                         cudaFuncAttributeMaxDynamicSharedMemorySize, SMEM_NT);
    cudaFuncSetAttribute(tc_gemm<false, false, false>,
                         cudaFuncAttributeMaxDynamicSharedMemorySize, SMEM_NN);

    // 1. tf32-round x and the three weight matrices
    cvt_tf32_kernel<<<1024, 256>>>(x,  Xc, M * D / 4);
    cvt_tf32_kernel<<<256,  256>>>(Wq, Wc + 0 * D * D, D * D / 4);
    cvt_tf32_kernel<<<256,  256>>>(Wk, Wc + 1 * D * D, D * D / 4);
    cvt_tf32_kernel<<<256,  256>>>(Wv, Wc + 2 * D * D, D * D / 4);

    // 2. QKV projections (epilogue rounds outputs to tf32)
    {
        dim3 grid(D / 128, M / 128), thr(128);
        tc_gemm<false, true, true><<<grid, thr, SMEM_NN>>>(Xc, Wc + 0 * D * D, bq, Q, M, D, D, 1.0f);
        tc_gemm<false, true, true><<<grid, thr, SMEM_NN>>>(Xc, Wc + 1 * D * D, bk, K, M, D, D, 1.0f);
        tc_gemm<false, true, true><<<grid, thr, SMEM_NN>>>(Xc, Wc + 2 * D * D, bv, V, M, D, D, 1.0f);
    }

    // 3. S = (1/32) * Q @ K^T
    {
        dim3 grid(M / 128, M / 128), thr(128);
        tc_gemm<true, false, false><<<grid, thr, SMEM_NT>>>(Q, K, nullptr, S, M, M, D, 1.0f / 32.0f);
    }

    // 4. softmax rows (writes tf32-rounded probs)
    softmax_rows_kernel<<<M, 256>>>(S, M);

    // 5. out = P @ V (full fp32 output)
    {
        dim3 grid(D / 128, M / 128), thr(128);
        tc_gemm<false, false, false><<<grid, thr, SMEM_NN>>>(S, V, nullptr, out, M, D, M, 1.0f);
    }
}

// round 4
// speedup vs baseline: 7.3029x; 2.2347x over previous
#include <cuda_runtime.h>
#include <cuda_fp16.h>
#include <math.h>
#include <stdint.h>

#define NTOK 4096
#define DMODEL 1024

// Scratch (no cudaMalloc allowed)
__device__ __half g_Xh[NTOK * DMODEL];
__device__ __half g_Wt[3 * DMODEL * DMODEL];   // W^T as half (q|k|v)
__device__ __half g_Qh[NTOK * DMODEL];
__device__ __half g_Kh[NTOK * DMODEL];
__device__ __half g_Vh[NTOK * DMODEL];
__device__ __half g_Vt[DMODEL * NTOK];         // V^T as half
__device__ float  g_S[(size_t)NTOK * NTOK];    // scores fp32
__device__ __half g_P[(size_t)NTOK * NTOK];    // softmax probs half

// ---------------------------------------------------------------------------
// PTX helpers
// ---------------------------------------------------------------------------
__device__ __forceinline__ void cp_async16(uint32_t smem_addr, const void* gptr) {
    asm volatile("cp.async.cg.shared.global [%0], [%1], 16;\n"
                 :: "r"(smem_addr), "l"(gptr));
}
__device__ __forceinline__ void cp_commit() {
    asm volatile("cp.async.commit_group;\n");
}
template <int N>
__device__ __forceinline__ void cp_wait() {
    asm volatile("cp.async.wait_group %0;\n" :: "n"(N));
}

__device__ __forceinline__ void ldmatrix_x4(uint32_t& r0, uint32_t& r1,
                                            uint32_t& r2, uint32_t& r3,
                                            uint32_t addr) {
    asm volatile("ldmatrix.sync.aligned.m8n8.x4.shared.b16 {%0,%1,%2,%3}, [%4];"
                 : "=r"(r0), "=r"(r1), "=r"(r2), "=r"(r3) : "r"(addr));
}

__device__ __forceinline__ void mma_f16(float (&d)[4], const uint32_t (&a)[4],
                                        uint32_t b0, uint32_t b1) {
    asm volatile(
        "mma.sync.aligned.m16n8k16.row.col.f32.f16.f16.f32 "
        "{%0,%1,%2,%3}, {%4,%5,%6,%7}, {%8,%9}, {%0,%1,%2,%3};"
        : "+f"(d[0]), "+f"(d[1]), "+f"(d[2]), "+f"(d[3])
        : "r"(a[0]), "r"(a[1]), "r"(a[2]), "r"(a[3]), "r"(b0), "r"(b1));
}

// ---------------------------------------------------------------------------
// fp16 NT GEMM: C[M,N] = alpha * A[M,K] @ B'[N,K]^T (+ fp32 bias)
// A, B' half, row-major k-contiguous. 256 threads. CTA tile 128x256, BK=64
// halves (128B rows, SW128 swizzle). 3-stage cp.async pipeline.
// 8 warps, each a 64x64 warp tile via m16n8k16.
// ---------------------------------------------------------------------------
#define BM 128
#define BN 256
#define BKH 64
#define A_BYTES (BM * 128)                  // 16384
#define B_BYTES (BN * 128)                  // 32768
#define STAGE_BYTES (A_BYTES + B_BYTES)     // 49152
#define STAGES 3
#define GEMM_SMEM (STAGES * STAGE_BYTES)    // 147456

__device__ __forceinline__ uint32_t swz(int row, int c8) {
    return (uint32_t)(row * 128 + ((c8 ^ (row & 7)) << 4));
}

template <bool HAS_BIAS, bool OUT_F32>
__global__ __launch_bounds__(256, 1)
void hgemm_nt(const __half* __restrict__ A, const __half* __restrict__ Bp,
              const float* __restrict__ bias, void* __restrict__ Cv,
              int M, int N, int K, float alpha)
{
    extern __shared__ __align__(1024) char smem[];
    const uint32_t sb = (uint32_t)__cvta_generic_to_shared(smem);
    const int tid = threadIdx.x, lane = tid & 31, warp = tid >> 5;
    const int wm = (warp >> 2) * 64, wn = (warp & 3) * 64;
    const int bm = blockIdx.y * BM, bn = blockIdx.x * BN;
    const int nch = K / BKH;

    float acc[4][8][4];
#pragma unroll
    for (int i = 0; i < 4; i++)
#pragma unroll
        for (int j = 0; j < 8; j++)
#pragma unroll
            for (int v = 0; v < 4; v++) acc[i][j][v] = 0.0f;

    auto issue = [&](int c) {
        const int s = c % STAGES;
        const int k0 = c * BKH;
        const uint32_t abase = sb + s * STAGE_BYTES;
        const uint32_t bbase = abase + A_BYTES;
        // A tile: 128 rows x 8 x 16B -> 4 per thread
#pragma unroll
        for (int i = 0; i < 4; i++) {
            int id = i * 256 + tid;
            int row = id >> 3, c8 = id & 7;
            cp_async16(abase + swz(row, c8),
                       A + (size_t)(bm + row) * K + k0 + c8 * 8);
        }
        // B tile: 256 rows x 8 x 16B -> 8 per thread
#pragma unroll
        for (int i = 0; i < 8; i++) {
            int id = i * 256 + tid;
            int row = id >> 3, c8 = id & 7;
            cp_async16(bbase + swz(row, c8),
                       Bp + (size_t)(bn + row) * K + k0 + c8 * 8);
        }
        cp_commit();
    };

    issue(0);
    issue(1);

    for (int c = 0; c < nch; c++) {
        if (c + 1 < nch) cp_wait<1>(); else cp_wait<0>();
        __syncthreads();
        if (c + 2 < nch) issue(c + 2);

        const uint32_t abase = sb + (c % STAGES) * STAGE_BYTES;
        const uint32_t bbase = abase + A_BYTES;

#pragma unroll
        for (int ks = 0; ks < 4; ks++) {
            uint32_t af[4][4];
#pragma unroll
            for (int mt = 0; mt < 4; mt++) {
                int row = wm + mt * 16 + (lane & 15);
                int c8  = 2 * ks + (lane >> 4);
                ldmatrix_x4(af[mt][0], af[mt][1], af[mt][2], af[mt][3],
                            abase + swz(row, c8));
            }
            uint32_t bf[4][4];
#pragma unroll
            for (int p = 0; p < 4; p++) {
                int row = wn + p * 16 + (lane & 7) + ((lane >> 4) << 3);
                int c8  = 2 * ks + ((lane >> 3) & 1);
                ldmatrix_x4(bf[p][0], bf[p][1], bf[p][2], bf[p][3],
                            bbase + swz(row, c8));
            }
#pragma unroll
            for (int mt = 0; mt < 4; mt++)
#pragma unroll
                for (int p = 0; p < 4; p++) {
                    mma_f16(acc[mt][2 * p],     af[mt], bf[p][0], bf[p][1]);
                    mma_f16(acc[mt][2 * p + 1], af[mt], bf[p][2], bf[p][3]);
                }
        }
    }

    // epilogue: c0,c1 -> row (lane>>2), cols 2*(lane&3); c2,c3 -> row+8
    const int r0 = lane >> 2, cc = (lane & 3) * 2;
#pragma unroll
    for (int mt = 0; mt < 4; mt++) {
#pragma unroll
        for (int nt = 0; nt < 8; nt++) {
            const int row = bm + wm + mt * 16 + r0;
            const int col = bn + wn + nt * 8 + cc;
            float v0 = acc[mt][nt][0] * alpha;
            float v1 = acc[mt][nt][1] * alpha;
            float v2 = acc[mt][nt][2] * alpha;
            float v3 = acc[mt][nt][3] * alpha;
            if (HAS_BIAS) {
                float b0 = bias[col], b1 = bias[col + 1];
                v0 += b0; v1 += b1; v2 += b0; v3 += b1;
            }
            if (OUT_F32) {
                float* C = (float*)Cv;
                *reinterpret_cast<float2*>(C + (size_t)row * N + col) = make_float2(v0, v1);
                *reinterpret_cast<float2*>(C + (size_t)(row + 8) * N + col) = make_float2(v2, v3);
            } else {
                __half* C = (__half*)Cv;
                *reinterpret_cast<__half2*>(C + (size_t)row * N + col) = __floats2half2_rn(v0, v1);
                *reinterpret_cast<__half2*>(C + (size_t)(row + 8) * N + col) = __floats2half2_rn(v2, v3);
            }
        }
    }
}

// ---------------------------------------------------------------------------
// Conversions / transposes
// ---------------------------------------------------------------------------
__global__ __launch_bounds__(256)
void cvt_f2h_kernel(const float* __restrict__ in, __half* __restrict__ out, int n4)
{
    int i = blockIdx.x * 256 + threadIdx.x;
    int stride = gridDim.x * 256;
    for (; i < n4; i += stride) {
        float4 v = reinterpret_cast<const float4*>(in)[i];
        __half2* o = reinterpret_cast<__half2*>(out) + 2 * i;
        o[0] = __floats2half2_rn(v.x, v.y);
        o[1] = __floats2half2_rn(v.z, v.w);
    }
}

// out[c][r] = (half) in[r][c]; in R x C fp32
__global__ __launch_bounds__(256)
void transpose_f2h_kernel(const float* __restrict__ in, __half* __restrict__ out,
                          int R, int C)
{
    __shared__ float t[32][33];
    const int bx = blockIdx.x * 32, by = blockIdx.y * 32;
    const int x = threadIdx.x;
#pragma unroll
    for (int i = threadIdx.y; i < 32; i += 8)
        t[i][x] = in[(size_t)(by + i) * C + bx + x];
    __syncthreads();
#pragma unroll
    for (int i = threadIdx.y; i < 32; i += 8)
        out[(size_t)(bx + i) * R + by + x] = __float2half_rn(t[x][i]);
}

// out[c][r] = in[r][c]; in R x C half
__global__ __launch_bounds__(256)
void transpose_h2h_kernel(const __half* __restrict__ in, __half* __restrict__ out,
                          int R, int C)
{
    __shared__ __half t[32][33];
    const int bx = blockIdx.x * 32, by = blockIdx.y * 32;
    const int x = threadIdx.x;
#pragma unroll
    for (int i = threadIdx.y; i < 32; i += 8)
        t[i][x] = in[(size_t)(by + i) * C + bx + x];
    __syncthreads();
#pragma unroll
    for (int i = threadIdx.y; i < 32; i += 8)
        out[(size_t)(bx + i) * R + by + x] = t[x][i];
}

// ---------------------------------------------------------------------------
// Row softmax: fp32 scores in S, half probs out to P. 256 thr/row, N=4096.
// ---------------------------------------------------------------------------
__global__ __launch_bounds__(256)
void softmax_rows_kernel(const float* __restrict__ S, __half* __restrict__ P, int N)
{
    __shared__ float redm[8];
    __shared__ float reds[8];
    const int tid = threadIdx.x, lane = tid & 31, w = tid >> 5;
    const float4* p = reinterpret_cast<const float4*>(S + (size_t)blockIdx.x * N);
    __half2* po = reinterpret_cast<__half2*>(P + (size_t)blockIdx.x * N);

    float4 v[4];
#pragma unroll
    for (int i = 0; i < 4; i++) v[i] = p[tid + 256 * i];

    float m = -INFINITY;
#pragma unroll
    for (int i = 0; i < 4; i++)
        m = fmaxf(m, fmaxf(fmaxf(v[i].x, v[i].y), fmaxf(v[i].z, v[i].w)));
#pragma unroll
    for (int o = 16; o; o >>= 1) m = fmaxf(m, __shfl_xor_sync(~0u, m, o));
    if (lane == 0) redm[w] = m;
    __syncthreads();
    float mb = redm[0];
#pragma unroll
    for (int i = 1; i < 8; i++) mb = fmaxf(mb, redm[i]);

    float sum = 0.0f;
#pragma unroll
    for (int i = 0; i < 4; i++) {
        v[i].x = __expf(v[i].x - mb); v[i].y = __expf(v[i].y - mb);
        v[i].z = __expf(v[i].z - mb); v[i].w = __expf(v[i].w - mb);
        sum += v[i].x + v[i].y + v[i].z + v[i].w;
    }
#pragma unroll
    for (int o = 16; o; o >>= 1) sum += __shfl_xor_sync(~0u, sum, o);
    if (lane == 0) reds[w] = sum;
    __syncthreads();
    float sb = 0.0f;
#pragma unroll
    for (int i = 0; i < 8; i++) sb += reds[i];
    const float inv = 1.0f / sb;

#pragma unroll
    for (int i = 0; i < 4; i++) {
        po[(tid + 256 * i) * 2 + 0] = __floats2half2_rn(v[i].x * inv, v[i].y * inv);
        po[(tid + 256 * i) * 2 + 1] = __floats2half2_rn(v[i].z * inv, v[i].w * inv);
    }
}

// ---------------------------------------------------------------------------
extern "C" void kernel_launch(void* const* d_in, const int* in_sizes, int n_in,
                              void* d_out, int out_size)
{
    const float* x  = (const float*)d_in[0];
    const float* Wq = (const float*)d_in[1];
    const float* Wk = (const float*)d_in[2];
    const float* Wv = (const float*)d_in[3];
    const float* bq = (const float*)d_in[4];
    const float* bk = (const float*)d_in[5];
    const float* bv = (const float*)d_in[6];
    float* out = (float*)d_out;

    __half *Xh, *Wt, *Qh, *Kh, *Vh, *Vt, *P;
    float *S;
    cudaGetSymbolAddress((void**)&Xh, g_Xh);
    cudaGetSymbolAddress((void**)&Wt, g_Wt);
    cudaGetSymbolAddress((void**)&Qh, g_Qh);
    cudaGetSymbolAddress((void**)&Kh, g_Kh);
    cudaGetSymbolAddress((void**)&Vh, g_Vh);
    cudaGetSymbolAddress((void**)&Vt, g_Vt);
    cudaGetSymbolAddress((void**)&S,  g_S);
    cudaGetSymbolAddress((void**)&P,  g_P);

    const int M = NTOK, D = DMODEL;

    cudaFuncSetAttribute(hgemm_nt<true,  false>,
                         cudaFuncAttributeMaxDynamicSharedMemorySize, GEMM_SMEM);
    cudaFuncSetAttribute(hgemm_nt<false, true>,
                         cudaFuncAttributeMaxDynamicSharedMemorySize, GEMM_SMEM);

    // 1. x -> half; W -> half transposed
    cvt_f2h_kernel<<<512, 256>>>(x, Xh, M * D / 4);
    {
        dim3 g(D / 32, D / 32), t(32, 8);
        transpose_f2h_kernel<<<g, t>>>(Wq, Wt + 0 * D * D, D, D);
        transpose_f2h_kernel<<<g, t>>>(Wk, Wt + 1 * D * D, D, D);
        transpose_f2h_kernel<<<g, t>>>(Wv, Wt + 2 * D * D, D, D);
    }

    // 2. QKV projections (half out)
    {
        dim3 grid(D / BN, M / BM);
        hgemm_nt<true, false><<<grid, 256, GEMM_SMEM>>>(Xh, Wt + 0 * D * D, bq, Qh, M, D, D, 1.0f);
        hgemm_nt<true, false><<<grid, 256, GEMM_SMEM>>>(Xh, Wt + 1 * D * D, bk, Kh, M, D, D, 1.0f);
        hgemm_nt<true, false><<<grid, 256, GEMM_SMEM>>>(Xh, Wt + 2 * D * D, bv, Vh, M, D, D, 1.0f);
    }

    // 3. V^T for PV GEMM
    {
        dim3 g(D / 32, M / 32), t(32, 8);
        transpose_h2h_kernel<<<g, t>>>(Vh, Vt, M, D);
    }

    // 4. S = (1/32) * Q @ K^T  (fp32 out)
    {
        dim3 grid(M / BN, M / BM);
        hgemm_nt<false, true><<<grid, 256, GEMM_SMEM>>>(Qh, Kh, nullptr, S, M, M, D, 1.0f / 32.0f);
    }

    // 5. softmax -> half P
    softmax_rows_kernel<<<M, 256>>>(S, P, M);

    // 6. out = P @ Vt^T (fp32 out)
    {
        dim3 grid(D / BN, M / BM);
        hgemm_nt<false, true><<<grid, 256, GEMM_SMEM>>>(P, Vt, nullptr, out, M, D, M, 1.0f);
    }
}

// round 5
// speedup vs baseline: 7.4733x; 1.0233x over previous
#include <cuda_runtime.h>
#include <cuda_fp16.h>
#include <math.h>
#include <stdint.h>

#define NTOK 4096
#define DMODEL 1024
#define D3 (3 * DMODEL)

// Scratch (no cudaMalloc allowed)
__device__ __half g_Xh[NTOK * DMODEL];
__device__ __half g_Wt[D3 * DMODEL];            // [3*1024 outfeat, 1024 infeat] half
__device__ float  g_bcat[D3];                   // bq|bk|bv
__device__ __half g_QKV[NTOK * D3];             // Q|K|V interleaved, ld=3072
__device__ __half g_Vt[DMODEL * NTOK];          // V^T half, ld=4096
__device__ __half g_E[(size_t)NTOK * NTOK];     // unnormalized exp scores, half
__device__ float  g_rowsum[NTOK];

// ---------------------------------------------------------------------------
// PTX helpers
// ---------------------------------------------------------------------------
__device__ __forceinline__ void cp_async16(uint32_t smem_addr, const void* gptr) {
    asm volatile("cp.async.cg.shared.global [%0], [%1], 16;\n"
                 :: "r"(smem_addr), "l"(gptr));
}
__device__ __forceinline__ void cp_commit() {
    asm volatile("cp.async.commit_group;\n");
}
template <int N>
__device__ __forceinline__ void cp_wait() {
    asm volatile("cp.async.wait_group %0;\n" :: "n"(N));
}

__device__ __forceinline__ void ldmatrix_x4(uint32_t& r0, uint32_t& r1,
                                            uint32_t& r2, uint32_t& r3,
                                            uint32_t addr) {
    asm volatile("ldmatrix.sync.aligned.m8n8.x4.shared.b16 {%0,%1,%2,%3}, [%4];"
                 : "=r"(r0), "=r"(r1), "=r"(r2), "=r"(r3) : "r"(addr));
}

__device__ __forceinline__ void mma_f16(float (&d)[4], const uint32_t (&a)[4],
                                        uint32_t b0, uint32_t b1) {
    asm volatile(
        "mma.sync.aligned.m16n8k16.row.col.f32.f16.f16.f32 "
        "{%0,%1,%2,%3}, {%4,%5,%6,%7}, {%8,%9}, {%0,%1,%2,%3};"
        : "+f"(d[0]), "+f"(d[1]), "+f"(d[2]), "+f"(d[3])
        : "r"(a[0]), "r"(a[1]), "r"(a[2]), "r"(a[3]), "r"(b0), "r"(b1));
}

// ---------------------------------------------------------------------------
// fp16 NT GEMM with leading dims: C[M,N] = f( alpha * A[M,K] @ B'[N,K]^T )
// MODE 0: half out, + bias            (QKV projection)
// MODE 1: half out, exp(alpha*acc)    (QK^T -> E)
// MODE 2: f32 out, * (1/rowsum[row])  (PV -> O)
// CTA tile 128x256, BK=64 halves, SW128 swizzle, 4-stage cp.async.
// ---------------------------------------------------------------------------
#define BM 128
#define BN 256
#define BKH 64
#define A_BYTES (BM * 128)
#define B_BYTES (BN * 128)
#define STAGE_BYTES (A_BYTES + B_BYTES)     // 49152
#define STAGES 4
#define GEMM_SMEM (STAGES * STAGE_BYTES)    // 196608

__device__ __forceinline__ uint32_t swz(int row, int c8) {
    return (uint32_t)(row * 128 + ((c8 ^ (row & 7)) << 4));
}

template <int MODE>
__global__ __launch_bounds__(256, 1)
void hgemm_nt(const __half* __restrict__ A, int lda,
              const __half* __restrict__ Bp, int ldb,
              const float* __restrict__ aux,      // bias (MODE0) / rowsum (MODE2)
              void* __restrict__ Cv, int ldc,
              int M, int N, int K, float alpha)
{
    extern __shared__ __align__(1024) char smem[];
    const uint32_t sb = (uint32_t)__cvta_generic_to_shared(smem);
    const int tid = threadIdx.x, lane = tid & 31, warp = tid >> 5;
    const int wm = (warp >> 2) * 64, wn = (warp & 3) * 64;
    const int bm = blockIdx.y * BM, bn = blockIdx.x * BN;
    const int nch = K / BKH;

    float acc[4][8][4];
#pragma unroll
    for (int i = 0; i < 4; i++)
#pragma unroll
        for (int j = 0; j < 8; j++)
#pragma unroll
            for (int v = 0; v < 4; v++) acc[i][j][v] = 0.0f;

    auto issue = [&](int c) {
        const int s = c % STAGES;
        const int k0 = c * BKH;
        const uint32_t abase = sb + s * STAGE_BYTES;
        const uint32_t bbase = abase + A_BYTES;
#pragma unroll
        for (int i = 0; i < 4; i++) {
            int id = i * 256 + tid;
            int row = id >> 3, c8 = id & 7;
            cp_async16(abase + swz(row, c8),
                       A + (size_t)(bm + row) * lda + k0 + c8 * 8);
        }
#pragma unroll
        for (int i = 0; i < 8; i++) {
            int id = i * 256 + tid;
            int row = id >> 3, c8 = id & 7;
            cp_async16(bbase + swz(row, c8),
                       Bp + (size_t)(bn + row) * ldb + k0 + c8 * 8);
        }
        cp_commit();
    };

    issue(0);
    issue(1);
    issue(2);

    for (int c = 0; c < nch; c++) {
        if (c + 2 < nch) cp_wait<2>();
        else if (c + 1 < nch) cp_wait<1>();
        else cp_wait<0>();
        __syncthreads();
        if (c + 3 < nch) issue(c + 3);

        const uint32_t abase = sb + (c % STAGES) * STAGE_BYTES;
        const uint32_t bbase = abase + A_BYTES;

#pragma unroll
        for (int ks = 0; ks < 4; ks++) {
            uint32_t af[4][4];
#pragma unroll
            for (int mt = 0; mt < 4; mt++) {
                int row = wm + mt * 16 + (lane & 15);
                int c8  = 2 * ks + (lane >> 4);
                ldmatrix_x4(af[mt][0], af[mt][1], af[mt][2], af[mt][3],
                            abase + swz(row, c8));
            }
            uint32_t bf[4][4];
#pragma unroll
            for (int p = 0; p < 4; p++) {
                int row = wn + p * 16 + (lane & 7) + ((lane >> 4) << 3);
                int c8  = 2 * ks + ((lane >> 3) & 1);
                ldmatrix_x4(bf[p][0], bf[p][1], bf[p][2], bf[p][3],
                            bbase + swz(row, c8));
            }
#pragma unroll
            for (int mt = 0; mt < 4; mt++)
#pragma unroll
                for (int p = 0; p < 4; p++) {
                    mma_f16(acc[mt][2 * p],     af[mt], bf[p][0], bf[p][1]);
                    mma_f16(acc[mt][2 * p + 1], af[mt], bf[p][2], bf[p][3]);
                }
        }
    }

    // epilogue
    const int r0 = lane >> 2, cc = (lane & 3) * 2;
#pragma unroll
    for (int mt = 0; mt < 4; mt++) {
        float inv0 = 1.0f, inv1 = 1.0f;
        if (MODE == 2) {
            inv0 = 1.0f / aux[bm + wm + mt * 16 + r0];
            inv1 = 1.0f / aux[bm + wm + mt * 16 + r0 + 8];
        }
#pragma unroll
        for (int nt = 0; nt < 8; nt++) {
            const int row = bm + wm + mt * 16 + r0;
            const int col = bn + wn + nt * 8 + cc;
            float v0 = acc[mt][nt][0] * alpha;
            float v1 = acc[mt][nt][1] * alpha;
            float v2 = acc[mt][nt][2] * alpha;
            float v3 = acc[mt][nt][3] * alpha;
            if (MODE == 0) {
                float b0 = aux[col], b1 = aux[col + 1];
                v0 += b0; v1 += b1; v2 += b0; v3 += b1;
                __half* C = (__half*)Cv;
                *reinterpret_cast<__half2*>(C + (size_t)row * ldc + col) = __floats2half2_rn(v0, v1);
                *reinterpret_cast<__half2*>(C + (size_t)(row + 8) * ldc + col) = __floats2half2_rn(v2, v3);
            } else if (MODE == 1) {
                v0 = __expf(v0); v1 = __expf(v1); v2 = __expf(v2); v3 = __expf(v3);
                __half* C = (__half*)Cv;
                *reinterpret_cast<__half2*>(C + (size_t)row * ldc + col) = __floats2half2_rn(v0, v1);
                *reinterpret_cast<__half2*>(C + (size_t)(row + 8) * ldc + col) = __floats2half2_rn(v2, v3);
            } else {
                float* C = (float*)Cv;
                *reinterpret_cast<float2*>(C + (size_t)row * ldc + col) =
                    make_float2(v0 * inv0, v1 * inv0);
                *reinterpret_cast<float2*>(C + (size_t)(row + 8) * ldc + col) =
                    make_float2(v2 * inv1, v3 * inv1);
            }
        }
    }
}

// ---------------------------------------------------------------------------
// Helpers: conversions, transposes, bias concat, row sums
// ---------------------------------------------------------------------------
__global__ __launch_bounds__(256)
void cvt_f2h_kernel(const float* __restrict__ in, __half* __restrict__ out, int n4)
{
    int i = blockIdx.x * 256 + threadIdx.x;
    int stride = gridDim.x * 256;
    for (; i < n4; i += stride) {
        float4 v = reinterpret_cast<const float4*>(in)[i];
        __half2* o = reinterpret_cast<__half2*>(out) + 2 * i;
        o[0] = __floats2half2_rn(v.x, v.y);
        o[1] = __floats2half2_rn(v.z, v.w);
    }
}

// out[c][r] = (half) in[r][c]; in R x C fp32, out ld = R
__global__ __launch_bounds__(256)
void transpose_f2h_kernel(const float* __restrict__ in, __half* __restrict__ out,
                          int R, int C)
{
    __shared__ float t[32][33];
    const int bx = blockIdx.x * 32, by = blockIdx.y * 32;
    const int x = threadIdx.x;
#pragma unroll
    for (int i = threadIdx.y; i < 32; i += 8)
        t[i][x] = in[(size_t)(by + i) * C + bx + x];
    __syncthreads();
#pragma unroll
    for (int i = threadIdx.y; i < 32; i += 8)
        out[(size_t)(bx + i) * R + by + x] = __float2half_rn(t[x][i]);
}

// out[c][r] = in[r][c]; in R x C half with leading dim ldin, out ld = R
__global__ __launch_bounds__(256)
void transpose_h2h_kernel(const __half* __restrict__ in, int ldin,
                          __half* __restrict__ out, int R, int C)
{
    __shared__ __half t[32][33];
    const int bx = blockIdx.x * 32, by = blockIdx.y * 32;
    const int x = threadIdx.x;
#pragma unroll
    for (int i = threadIdx.y; i < 32; i += 8)
        t[i][x] = in[(size_t)(by + i) * ldin + bx + x];
    __syncthreads();
#pragma unroll
    for (int i = threadIdx.y; i < 32; i += 8)
        out[(size_t)(bx + i) * R + by + x] = t[x][i];
}

__global__ void cat_bias_kernel(const float* a, const float* b, const float* c,
                                float* out, int n)
{
    int i = blockIdx.x * 256 + threadIdx.x;
    if (i < n) out[i] = a[i];
    else if (i < 2 * n) out[i] = b[i - n];
    else if (i < 3 * n) out[i] = c[i - 2 * n];
}

// rowsum[r] = sum of E[r][:] (deterministic order). 256 thr/row, N=4096.
__global__ __launch_bounds__(256)
void rowsum_kernel(const __half* __restrict__ E, float* __restrict__ rs, int N)
{
    __shared__ float red[8];
    const int tid = threadIdx.x, lane = tid & 31, w = tid >> 5;
    const __half2* p = reinterpret_cast<const __half2*>(E + (size_t)blockIdx.x * N);
    float sum = 0.0f;
#pragma unroll
    for (int i = 0; i < 8; i++) {
        float2 v = __half22float2(p[tid + 256 * i]);
        sum += v.x + v.y;
    }
#pragma unroll
    for (int o = 16; o; o >>= 1) sum += __shfl_xor_sync(~0u, sum, o);
    if (lane == 0) red[w] = sum;
    __syncthreads();
    if (tid == 0) {
        float s = 0.0f;
#pragma unroll
        for (int i = 0; i < 8; i++) s += red[i];
        rs[blockIdx.x] = s;
    }
}

// ---------------------------------------------------------------------------
extern "C" void kernel_launch(void* const* d_in, const int* in_sizes, int n_in,
                              void* d_out, int out_size)
{
    const float* x  = (const float*)d_in[0];
    const float* Wq = (const float*)d_in[1];
    const float* Wk = (const float*)d_in[2];
    const float* Wv = (const float*)d_in[3];
    const float* bq = (const float*)d_in[4];
    const float* bk = (const float*)d_in[5];
    const float* bv = (const float*)d_in[6];
    float* out = (float*)d_out;

    __half *Xh, *Wt, *QKV, *Vt, *E;
    float *bcat, *rowsum;
    cudaGetSymbolAddress((void**)&Xh,     g_Xh);
    cudaGetSymbolAddress((void**)&Wt,     g_Wt);
    cudaGetSymbolAddress((void**)&bcat,   g_bcat);
    cudaGetSymbolAddress((void**)&QKV,    g_QKV);
    cudaGetSymbolAddress((void**)&Vt,     g_Vt);
    cudaGetSymbolAddress((void**)&E,      g_E);
    cudaGetSymbolAddress((void**)&rowsum, g_rowsum);

    const int M = NTOK, D = DMODEL;

    cudaFuncSetAttribute(hgemm_nt<0>, cudaFuncAttributeMaxDynamicSharedMemorySize, GEMM_SMEM);
    cudaFuncSetAttribute(hgemm_nt<1>, cudaFuncAttributeMaxDynamicSharedMemorySize, GEMM_SMEM);
    cudaFuncSetAttribute(hgemm_nt<2>, cudaFuncAttributeMaxDynamicSharedMemorySize, GEMM_SMEM);

    // 1. x -> half; W -> half transposed (into concatenated [3072,1024]); bias cat
    cvt_f2h_kernel<<<512, 256>>>(x, Xh, M * D / 4);
    {
        dim3 g(D / 32, D / 32), t(32, 8);
        transpose_f2h_kernel<<<g, t>>>(Wq, Wt + 0 * D * D, D, D);
        transpose_f2h_kernel<<<g, t>>>(Wk, Wt + 1 * D * D, D, D);
        transpose_f2h_kernel<<<g, t>>>(Wv, Wt + 2 * D * D, D, D);
    }
    cat_bias_kernel<<<(D3 + 255) / 256, 256>>>(bq, bk, bv, bcat, D);

    // 2. fused QKV projection: [4096,3072] = Xh @ Wt^T + bcat
    {
        dim3 grid(D3 / BN, M / BM);
        hgemm_nt<0><<<grid, 256, GEMM_SMEM>>>(Xh, D, Wt, D, bcat, QKV, D3, M, D3, D, 1.0f);
    }

    // 3. V^T (view of QKV cols 2048..3071)
    {
        dim3 g(D / 32, M / 32), t(32, 8);
        transpose_h2h_kernel<<<g, t>>>(QKV + 2 * D, D3, Vt, M, D);
    }

    // 4. E = exp(Q @ K^T / 32)  (half, unnormalized)
    {
        dim3 grid(M / BN, M / BM);
        hgemm_nt<1><<<grid, 256, GEMM_SMEM>>>(QKV + 0 * D, D3, QKV + 1 * D, D3,
                                              nullptr, E, M, M, M, D, 1.0f / 32.0f);
    }

    // 5. rowsum[r] = sum E[r][:]
    rowsum_kernel<<<M, 256>>>(E, rowsum, M);

    // 6. out = (E @ Vt^T) / rowsum
    {
        dim3 grid(D / BN, M / BM);
        hgemm_nt<2><<<grid, 256, GEMM_SMEM>>>(E, M, Vt, M, rowsum, out, D, M, D, M, 1.0f);
    }
}

// round 7
// speedup vs baseline: 7.6803x; 1.0277x over previous
#include <cuda_runtime.h>
#include <cuda_fp16.h>
#include <math.h>
#include <stdint.h>

#define NTOK 4096
#define DMODEL 1024
#define D3 (3 * DMODEL)
#define NPART 64   // partial rowsums per row = (NTOK/BN) * 2 col-warps

// Scratch (no cudaMalloc allowed)
__device__ __half g_Xh[NTOK * DMODEL];
__device__ __half g_Wt[D3 * DMODEL];
__device__ float  g_bcat[D3];
__device__ __half g_QKV[NTOK * D3];
__device__ __half g_Vt[DMODEL * NTOK];
__device__ __half g_E[(size_t)NTOK * NTOK];
__device__ float  g_rsp[NTOK * NPART];   // per-(CTA,col-warp) partial row sums
__device__ float  g_rowsum[NTOK];

// ---------------------------------------------------------------------------
__device__ __forceinline__ void cp_async16(uint32_t smem_addr, const void* gptr) {
    asm volatile("cp.async.cg.shared.global [%0], [%1], 16;\n"
                 :: "r"(smem_addr), "l"(gptr));
}
__device__ __forceinline__ void cp_commit() {
    asm volatile("cp.async.commit_group;\n");
}
template <int N>
__device__ __forceinline__ void cp_wait() {
    asm volatile("cp.async.wait_group %0;\n" :: "n"(N));
}

__device__ __forceinline__ void ldmatrix_x4(uint32_t& r0, uint32_t& r1,
                                            uint32_t& r2, uint32_t& r3,
                                            uint32_t addr) {
    asm volatile("ldmatrix.sync.aligned.m8n8.x4.shared.b16 {%0,%1,%2,%3}, [%4];"
                 : "=r"(r0), "=r"(r1), "=r"(r2), "=r"(r3) : "r"(addr));
}

__device__ __forceinline__ void mma_f16(float (&d)[4], const uint32_t (&a)[4],
                                        uint32_t b0, uint32_t b1) {
    asm volatile(
        "mma.sync.aligned.m16n8k16.row.col.f32.f16.f16.f32 "
        "{%0,%1,%2,%3}, {%4,%5,%6,%7}, {%8,%9}, {%0,%1,%2,%3};"
        : "+f"(d[0]), "+f"(d[1]), "+f"(d[2]), "+f"(d[3])
        : "r"(a[0]), "r"(a[1]), "r"(a[2]), "r"(a[3]), "r"(b0), "r"(b1));
}

// ---------------------------------------------------------------------------
// fp16 NT GEMM, CTA tile 128x128, 4 warps (64x64 warp tiles), BK=64, 3 stages.
// 2 CTAs/SM. MODE 0: +bias half out. MODE 1: exp() half out + partial rowsums.
// MODE 2: f32 out scaled by 1/rowsum[row].
// ---------------------------------------------------------------------------
#define BM 128
#define BN 128
#define BKH 64
#define A_BYTES (BM * 128)
#define B_BYTES (BN * 128)
#define STAGE_BYTES (A_BYTES + B_BYTES)     // 32768
#define STAGES 3
#define GEMM_SMEM (STAGES * STAGE_BYTES)    // 98304

__device__ __forceinline__ uint32_t swz(int row, int c8) {
    return (uint32_t)(row * 128 + ((c8 ^ (row & 7)) << 4));
}

template <int MODE>
__global__ __launch_bounds__(128, 2)
void hgemm_nt(const __half* __restrict__ A, int lda,
              const __half* __restrict__ Bp, int ldb,
              const float* __restrict__ aux,      // bias (0) / rowsum (2)
              float* __restrict__ rsp,            // partial rowsums (1)
              void* __restrict__ Cv, int ldc,
              int M, int N, int K, float alpha)
{
    extern __shared__ __align__(1024) char smem[];
    const uint32_t sb = (uint32_t)__cvta_generic_to_shared(smem);
    const int tid = threadIdx.x, lane = tid & 31, warp = tid >> 5;
    const int wm = (warp >> 1) * 64, wn = (warp & 1) * 64;
    const int bm = blockIdx.y * BM, bn = blockIdx.x * BN;
    const int nch = K / BKH;

    float acc[4][8][4];
#pragma unroll
    for (int i = 0; i < 4; i++)
#pragma unroll
        for (int j = 0; j < 8; j++)
#pragma unroll
            for (int v = 0; v < 4; v++) acc[i][j][v] = 0.0f;

    auto issue = [&](int c) {
        const int s = c % STAGES;
        const int k0 = c * BKH;
        const uint32_t abase = sb + s * STAGE_BYTES;
        const uint32_t bbase = abase + A_BYTES;
#pragma unroll
        for (int i = 0; i < 8; i++) {
            int id = i * 128 + tid;
            int row = id >> 3, c8 = id & 7;
            cp_async16(abase + swz(row, c8),
                       A + (size_t)(bm + row) * lda + k0 + c8 * 8);
        }
#pragma unroll
        for (int i = 0; i < 8; i++) {
            int id = i * 128 + tid;
            int row = id >> 3, c8 = id & 7;
            cp_async16(bbase + swz(row, c8),
                       Bp + (size_t)(bn + row) * ldb + k0 + c8 * 8);
        }
        cp_commit();
    };

    issue(0);
    issue(1);

    for (int c = 0; c < nch; c++) {
        if (c + 1 < nch) cp_wait<1>(); else cp_wait<0>();
        __syncthreads();
        if (c + 2 < nch) issue(c + 2);

        const uint32_t abase = sb + (c % STAGES) * STAGE_BYTES;
        const uint32_t bbase = abase + A_BYTES;

#pragma unroll
        for (int ks = 0; ks < 4; ks++) {
            uint32_t af[4][4];
#pragma unroll
            for (int mt = 0; mt < 4; mt++) {
                int row = wm + mt * 16 + (lane & 15);
                int c8  = 2 * ks + (lane >> 4);
                ldmatrix_x4(af[mt][0], af[mt][1], af[mt][2], af[mt][3],
                            abase + swz(row, c8));
            }
            uint32_t bf[4][4];
#pragma unroll
            for (int p = 0; p < 4; p++) {
                int row = wn + p * 16 + (lane & 7) + ((lane >> 4) << 3);
                int c8  = 2 * ks + ((lane >> 3) & 1);
                ldmatrix_x4(bf[p][0], bf[p][1], bf[p][2], bf[p][3],
                            bbase + swz(row, c8));
            }
#pragma unroll
            for (int mt = 0; mt < 4; mt++)
#pragma unroll
                for (int p = 0; p < 4; p++) {
                    mma_f16(acc[mt][2 * p],     af[mt], bf[p][0], bf[p][1]);
                    mma_f16(acc[mt][2 * p + 1], af[mt], bf[p][2], bf[p][3]);
                }
        }
    }

    // epilogue
    const int r0 = lane >> 2, cc = (lane & 3) * 2;
#pragma unroll
    for (int mt = 0; mt < 4; mt++) {
        const int row = bm + wm + mt * 16 + r0;
        float inv0 = 1.0f, inv1 = 1.0f;
        if (MODE == 2) { inv0 = 1.0f / aux[row]; inv1 = 1.0f / aux[row + 8]; }
        float s0 = 0.0f, s1 = 0.0f;
#pragma unroll
        for (int nt = 0; nt < 8; nt++) {
            const int col = bn + wn + nt * 8 + cc;
            float v0 = acc[mt][nt][0] * alpha;
            float v1 = acc[mt][nt][1] * alpha;
            float v2 = acc[mt][nt][2] * alpha;
            float v3 = acc[mt][nt][3] * alpha;
            if (MODE == 0) {
                float b0 = aux[col], b1 = aux[col + 1];
                v0 += b0; v1 += b1; v2 += b0; v3 += b1;
                __half* C = (__half*)Cv;
                *reinterpret_cast<__half2*>(C + (size_t)row * ldc + col) = __floats2half2_rn(v0, v1);
                *reinterpret_cast<__half2*>(C + (size_t)(row + 8) * ldc + col) = __floats2half2_rn(v2, v3);
            } else if (MODE == 1) {
                v0 = __expf(v0); v1 = __expf(v1); v2 = __expf(v2); v3 = __expf(v3);
                s0 += v0 + v1;  s1 += v2 + v3;
                __half* C = (__half*)Cv;
                *reinterpret_cast<__half2*>(C + (size_t)row * ldc + col) = __floats2half2_rn(v0, v1);
                *reinterpret_cast<__half2*>(C + (size_t)(row + 8) * ldc + col) = __floats2half2_rn(v2, v3);
            } else {
                float* C = (float*)Cv;
                *reinterpret_cast<float2*>(C + (size_t)row * ldc + col) =
                    make_float2(v0 * inv0, v1 * inv0);
                *reinterpret_cast<float2*>(C + (size_t)(row + 8) * ldc + col) =
                    make_float2(v2 * inv1, v3 * inv1);
            }
        }
        if (MODE == 1) {
            // sum the 4 lanes holding this row (lane bits 0..1 = column subsets)
            s0 += __shfl_xor_sync(~0u, s0, 1); s0 += __shfl_xor_sync(~0u, s0, 2);
            s1 += __shfl_xor_sync(~0u, s1, 1); s1 += __shfl_xor_sync(~0u, s1, 2);
            if ((lane & 3) == 0) {
                // one slot per (CTA col-block, col-warp): no write collisions
                const int part = blockIdx.x * 2 + (warp & 1);
                rsp[(size_t)row * NPART + part] = s0;
                rsp[(size_t)(row + 8) * NPART + part] = s1;
            }
        }
    }
}

// ---------------------------------------------------------------------------
__global__ __launch_bounds__(256)
void cvt_f2h_kernel(const float* __restrict__ in, __half* __restrict__ out, int n4)
{
    int i = blockIdx.x * 256 + threadIdx.x;
    int stride = gridDim.x * 256;
    for (; i < n4; i += stride) {
        float4 v = reinterpret_cast<const float4*>(in)[i];
        __half2* o = reinterpret_cast<__half2*>(out) + 2 * i;
        o[0] = __floats2half2_rn(v.x, v.y);
        o[1] = __floats2half2_rn(v.z, v.w);
    }
}

__global__ __launch_bounds__(256)
void transpose_f2h_kernel(const float* __restrict__ in, __half* __restrict__ out,
                          int R, int C)
{
    __shared__ float t[32][33];
    const int bx = blockIdx.x * 32, by = blockIdx.y * 32;
    const int x = threadIdx.x;
#pragma unroll
    for (int i = threadIdx.y; i < 32; i += 8)
        t[i][x] = in[(size_t)(by + i) * C + bx + x];
    __syncthreads();
#pragma unroll
    for (int i = threadIdx.y; i < 32; i += 8)
        out[(size_t)(bx + i) * R + by + x] = __float2half_rn(t[x][i]);
}

__global__ __launch_bounds__(256)
void transpose_h2h_kernel(const __half* __restrict__ in, int ldin,
                          __half* __restrict__ out, int R, int C)
{
    __shared__ __half t[32][33];
    const int bx = blockIdx.x * 32, by = blockIdx.y * 32;
    const int x = threadIdx.x;
#pragma unroll
    for (int i = threadIdx.y; i < 32; i += 8)
        t[i][x] = in[(size_t)(by + i) * ldin + bx + x];
    __syncthreads();
#pragma unroll
    for (int i = threadIdx.y; i < 32; i += 8)
        out[(size_t)(bx + i) * R + by + x] = t[x][i];
}

__global__ void cat_bias_kernel(const float* a, const float* b, const float* c,
                                float* out, int n)
{
    int i = blockIdx.x * 256 + threadIdx.x;
    if (i < n) out[i] = a[i];
    else if (i < 2 * n) out[i] = b[i - n];
    else if (i < 3 * n) out[i] = c[i - 2 * n];
}

// rowsum[r] = deterministic sum of the NPART partials of row r
__global__ __launch_bounds__(256)
void rowsum_reduce_kernel(const float* __restrict__ rsp, float* __restrict__ rs)
{
    int row = blockIdx.x * 256 + threadIdx.x;
    if (row < NTOK) {
        float s = 0.0f;
#pragma unroll
        for (int i = 0; i < NPART; i++) s += rsp[(size_t)row * NPART + i];
        rs[row] = s;
    }
}

// ---------------------------------------------------------------------------
extern "C" void kernel_launch(void* const* d_in, const int* in_sizes, int n_in,
                              void* d_out, int out_size)
{
    const float* x  = (const float*)d_in[0];
    const float* Wq = (const float*)d_in[1];
    const float* Wk = (const float*)d_in[2];
    const float* Wv = (const float*)d_in[3];
    const float* bq = (const float*)d_in[4];
    const float* bk = (const float*)d_in[5];
    const float* bv = (const float*)d_in[6];
    float* out = (float*)d_out;

    __half *Xh, *Wt, *QKV, *Vt, *E;
    float *bcat, *rsp, *rowsum;
    cudaGetSymbolAddress((void**)&Xh,     g_Xh);
    cudaGetSymbolAddress((void**)&Wt,     g_Wt);
    cudaGetSymbolAddress((void**)&bcat,   g_bcat);
    cudaGetSymbolAddress((void**)&QKV,    g_QKV);
    cudaGetSymbolAddress((void**)&Vt,     g_Vt);
    cudaGetSymbolAddress((void**)&E,      g_E);
    cudaGetSymbolAddress((void**)&rsp,    g_rsp);
    cudaGetSymbolAddress((void**)&rowsum, g_rowsum);

    const int M = NTOK, D = DMODEL;

    cudaFuncSetAttribute(hgemm_nt<0>, cudaFuncAttributeMaxDynamicSharedMemorySize, GEMM_SMEM);
    cudaFuncSetAttribute(hgemm_nt<1>, cudaFuncAttributeMaxDynamicSharedMemorySize, GEMM_SMEM);
    cudaFuncSetAttribute(hgemm_nt<2>, cudaFuncAttributeMaxDynamicSharedMemorySize, GEMM_SMEM);

    // 1. inputs -> half (W transposed+concatenated), bias concat
    cvt_f2h_kernel<<<512, 256>>>(x, Xh, M * D / 4);
    {
        dim3 g(D / 32, D / 32), t(32, 8);
        transpose_f2h_kernel<<<g, t>>>(Wq, Wt + 0 * D * D, D, D);
        transpose_f2h_kernel<<<g, t>>>(Wk, Wt + 1 * D * D, D, D);
        transpose_f2h_kernel<<<g, t>>>(Wv, Wt + 2 * D * D, D, D);
    }
    cat_bias_kernel<<<(D3 + 255) / 256, 256>>>(bq, bk, bv, bcat, D);

    // 2. fused QKV projection
    {
        dim3 grid(D3 / BN, M / BM);
        hgemm_nt<0><<<grid, 128, GEMM_SMEM>>>(Xh, D, Wt, D, bcat, nullptr, QKV, D3, M, D3, D, 1.0f);
    }

    // 3. V^T
    {
        dim3 g(D / 32, M / 32), t(32, 8);
        transpose_h2h_kernel<<<g, t>>>(QKV + 2 * D, D3, Vt, M, D);
    }

    // 4. E = exp(Q K^T / 32), partial rowsums from registers
    {
        dim3 grid(M / BN, M / BM);
        hgemm_nt<1><<<grid, 128, GEMM_SMEM>>>(QKV + 0 * D, D3, QKV + 1 * D, D3,
                                              nullptr, rsp, E, M, M, M, D, 1.0f / 32.0f);
    }

    // 5. reduce partials
    rowsum_reduce_kernel<<<(M + 255) / 256, 256>>>(rsp, rowsum);

    // 6. out = (E @ Vt^T) / rowsum
    {
        dim3 grid(D / BN, M / BM);
        hgemm_nt<2><<<grid, 128, GEMM_SMEM>>>(E, M, Vt, M, rowsum, nullptr, out, D, M, D, M, 1.0f);
    }
}

// round 8
// speedup vs baseline: 7.7743x; 1.0122x over previous
#include <cuda_runtime.h>
#include <cuda_fp16.h>
#include <math.h>
#include <stdint.h>

#define NTOK 4096
#define DMODEL 1024
#define D3 (3 * DMODEL)
#define NPART 64   // partial rowsums per row = (NTOK/BN) * 2 col-warps

// Scratch (no cudaMalloc allowed)
__device__ __half g_Xh[NTOK * DMODEL];
__device__ __half g_Wt[D3 * DMODEL];
__device__ float  g_bcat[D3];
__device__ __half g_QKV[NTOK * D3];
__device__ __half g_Vt[DMODEL * NTOK];
__device__ __half g_E[(size_t)NTOK * NTOK];
__device__ float  g_rsp[NTOK * NPART];
__device__ float  g_rowsum[NTOK];

// ---------------------------------------------------------------------------
__device__ __forceinline__ void cp_async16(uint32_t smem_addr, const void* gptr) {
    asm volatile("cp.async.cg.shared.global [%0], [%1], 16;\n"
                 :: "r"(smem_addr), "l"(gptr));
}
__device__ __forceinline__ void cp_commit() {
    asm volatile("cp.async.commit_group;\n");
}
template <int N>
__device__ __forceinline__ void cp_wait() {
    asm volatile("cp.async.wait_group %0;\n" :: "n"(N));
}

__device__ __forceinline__ void ldmatrix_x4(uint32_t& r0, uint32_t& r1,
                                            uint32_t& r2, uint32_t& r3,
                                            uint32_t addr) {
    asm volatile("ldmatrix.sync.aligned.m8n8.x4.shared.b16 {%0,%1,%2,%3}, [%4];"
                 : "=r"(r0), "=r"(r1), "=r"(r2), "=r"(r3) : "r"(addr));
}

__device__ __forceinline__ void mma_f16(float (&d)[4], const uint32_t (&a)[4],
                                        uint32_t b0, uint32_t b1) {
    asm volatile(
        "mma.sync.aligned.m16n8k16.row.col.f32.f16.f16.f32 "
        "{%0,%1,%2,%3}, {%4,%5,%6,%7}, {%8,%9}, {%0,%1,%2,%3};"
        : "+f"(d[0]), "+f"(d[1]), "+f"(d[2]), "+f"(d[3])
        : "r"(a[0]), "r"(a[1]), "r"(a[2]), "r"(a[3]), "r"(b0), "r"(b1));
}

// ---------------------------------------------------------------------------
// Persistent fp16 NT GEMM. CTA tile 128x128, 4 warps (64x64), BK=64, 3 stages,
// 2 CTAs/SM, grid = 296 persistent CTAs looping over tiles.
// MODE 0: +bias half out. MODE 1: exp() half out + partial rowsums.
// MODE 2: f32 out scaled by 1/rowsum[row].
// ---------------------------------------------------------------------------
#define BM 128
#define BN 128
#define BKH 64
#define A_BYTES (BM * 128)
#define B_BYTES (BN * 128)
#define STAGE_BYTES (A_BYTES + B_BYTES)     // 32768
#define STAGES 3
#define GEMM_SMEM (STAGES * STAGE_BYTES)    // 98304
#define PGRID 296

__device__ __forceinline__ uint32_t swz(int row, int c8) {
    return (uint32_t)(row * 128 + ((c8 ^ (row & 7)) << 4));
}

template <int MODE>
__global__ __launch_bounds__(128, 2)
void hgemm_nt(const __half* __restrict__ A, int lda,
              const __half* __restrict__ Bp, int ldb,
              const float* __restrict__ aux,      // bias (0) / rowsum (2)
              float* __restrict__ rsp,            // partial rowsums (1)
              void* __restrict__ Cv, int ldc,
              int nbm, int nbn, int K, int N, float alpha)
{
    extern __shared__ __align__(1024) char smem[];
    const uint32_t sb = (uint32_t)__cvta_generic_to_shared(smem);
    const int tid = threadIdx.x, lane = tid & 31, warp = tid >> 5;
    const int wm = (warp >> 1) * 64, wn = (warp & 1) * 64;
    const int nch = K / BKH;
    const int ntiles = nbm * nbn;

    for (int t = blockIdx.x; t < ntiles; t += gridDim.x) {
        const int bm = (t / nbn) * BM;
        const int tn = t % nbn;
        const int bn = tn * BN;

        float acc[4][8][4];
#pragma unroll
        for (int i = 0; i < 4; i++)
#pragma unroll
            for (int j = 0; j < 8; j++)
#pragma unroll
                for (int v = 0; v < 4; v++) acc[i][j][v] = 0.0f;

        auto issue = [&](int c) {
            const int s = c % STAGES;
            const int k0 = c * BKH;
            const uint32_t abase = sb + s * STAGE_BYTES;
            const uint32_t bbase = abase + A_BYTES;
#pragma unroll
            for (int i = 0; i < 8; i++) {
                int id = i * 128 + tid;
                int row = id >> 3, c8 = id & 7;
                cp_async16(abase + swz(row, c8),
                           A + (size_t)(bm + row) * lda + k0 + c8 * 8);
            }
#pragma unroll
            for (int i = 0; i < 8; i++) {
                int id = i * 128 + tid;
                int row = id >> 3, c8 = id & 7;
                cp_async16(bbase + swz(row, c8),
                           Bp + (size_t)(bn + row) * ldb + k0 + c8 * 8);
            }
            cp_commit();
        };

        // all warps must be done reading previous tile's smem before refill
        __syncthreads();

        issue(0);
        issue(1);

        for (int c = 0; c < nch; c++) {
            if (c + 1 < nch) cp_wait<1>(); else cp_wait<0>();
            __syncthreads();
            if (c + 2 < nch) issue(c + 2);

            const uint32_t abase = sb + (c % STAGES) * STAGE_BYTES;
            const uint32_t bbase = abase + A_BYTES;

#pragma unroll
            for (int ks = 0; ks < 4; ks++) {
                uint32_t af[4][4];
#pragma unroll
                for (int mt = 0; mt < 4; mt++) {
                    int row = wm + mt * 16 + (lane & 15);
                    int c8  = 2 * ks + (lane >> 4);
                    ldmatrix_x4(af[mt][0], af[mt][1], af[mt][2], af[mt][3],
                                abase + swz(row, c8));
                }
                uint32_t bf[4][4];
#pragma unroll
                for (int p = 0; p < 4; p++) {
                    int row = wn + p * 16 + (lane & 7) + ((lane >> 4) << 3);
                    int c8  = 2 * ks + ((lane >> 3) & 1);
                    ldmatrix_x4(bf[p][0], bf[p][1], bf[p][2], bf[p][3],
                                bbase + swz(row, c8));
                }
#pragma unroll
                for (int mt = 0; mt < 4; mt++)
#pragma unroll
                    for (int p = 0; p < 4; p++) {
                        mma_f16(acc[mt][2 * p],     af[mt], bf[p][0], bf[p][1]);
                        mma_f16(acc[mt][2 * p + 1], af[mt], bf[p][2], bf[p][3]);
                    }
            }
        }

        // epilogue
        const int r0 = lane >> 2, cc = (lane & 3) * 2;
#pragma unroll
        for (int mt = 0; mt < 4; mt++) {
            const int row = bm + wm + mt * 16 + r0;
            float inv0 = 1.0f, inv1 = 1.0f;
            if (MODE == 2) { inv0 = 1.0f / aux[row]; inv1 = 1.0f / aux[row + 8]; }
            float s0 = 0.0f, s1 = 0.0f;
#pragma unroll
            for (int nt = 0; nt < 8; nt++) {
                const int col = bn + wn + nt * 8 + cc;
                float v0 = acc[mt][nt][0] * alpha;
                float v1 = acc[mt][nt][1] * alpha;
                float v2 = acc[mt][nt][2] * alpha;
                float v3 = acc[mt][nt][3] * alpha;
                if (MODE == 0) {
                    float b0 = aux[col], b1 = aux[col + 1];
                    v0 += b0; v1 += b1; v2 += b0; v3 += b1;
                    __half* C = (__half*)Cv;
                    *reinterpret_cast<__half2*>(C + (size_t)row * ldc + col) = __floats2half2_rn(v0, v1);
                    *reinterpret_cast<__half2*>(C + (size_t)(row + 8) * ldc + col) = __floats2half2_rn(v2, v3);
                } else if (MODE == 1) {
                    v0 = __expf(v0); v1 = __expf(v1); v2 = __expf(v2); v3 = __expf(v3);
                    s0 += v0 + v1;  s1 += v2 + v3;
                    __half* C = (__half*)Cv;
                    *reinterpret_cast<__half2*>(C + (size_t)row * ldc + col) = __floats2half2_rn(v0, v1);
                    *reinterpret_cast<__half2*>(C + (size_t)(row + 8) * ldc + col) = __floats2half2_rn(v2, v3);
                } else {
                    float* C = (float*)Cv;
                    *reinterpret_cast<float2*>(C + (size_t)row * ldc + col) =
                        make_float2(v0 * inv0, v1 * inv0);
                    *reinterpret_cast<float2*>(C + (size_t)(row + 8) * ldc + col) =
                        make_float2(v2 * inv1, v3 * inv1);
                }
            }
            if (MODE == 1) {
                s0 += __shfl_xor_sync(~0u, s0, 1); s0 += __shfl_xor_sync(~0u, s0, 2);
                s1 += __shfl_xor_sync(~0u, s1, 1); s1 += __shfl_xor_sync(~0u, s1, 2);
                if ((lane & 3) == 0) {
                    const int part = tn * 2 + (warp & 1);   // tile col idx, NOT blockIdx
                    rsp[(size_t)row * NPART + part] = s0;
                    rsp[(size_t)(row + 8) * NPART + part] = s1;
                }
            }
        }
    }
}

// ---------------------------------------------------------------------------
__global__ __launch_bounds__(256)
void cvt_f2h_kernel(const float* __restrict__ in, __half* __restrict__ out, int n4)
{
    int i = blockIdx.x * 256 + threadIdx.x;
    int stride = gridDim.x * 256;
    for (; i < n4; i += stride) {
        float4 v = reinterpret_cast<const float4*>(in)[i];
        __half2* o = reinterpret_cast<__half2*>(out) + 2 * i;
        o[0] = __floats2half2_rn(v.x, v.y);
        o[1] = __floats2half2_rn(v.z, v.w);
    }
}

__global__ __launch_bounds__(256)
void transpose_f2h_kernel(const float* __restrict__ in, __half* __restrict__ out,
                          int R, int C)
{
    __shared__ float t[32][33];
    const int bx = blockIdx.x * 32, by = blockIdx.y * 32;
    const int x = threadIdx.x;
#pragma unroll
    for (int i = threadIdx.y; i < 32; i += 8)
        t[i][x] = in[(size_t)(by + i) * C + bx + x];
    __syncthreads();
#pragma unroll
    for (int i = threadIdx.y; i < 32; i += 8)
        out[(size_t)(bx + i) * R + by + x] = __float2half_rn(t[x][i]);
}

__global__ __launch_bounds__(256)
void transpose_h2h_kernel(const __half* __restrict__ in, int ldin,
                          __half* __restrict__ out, int R, int C)
{
    __shared__ __half t[32][33];
    const int bx = blockIdx.x * 32, by = blockIdx.y * 32;
    const int x = threadIdx.x;
#pragma unroll
    for (int i = threadIdx.y; i < 32; i += 8)
        t[i][x] = in[(size_t)(by + i) * ldin + bx + x];
    __syncthreads();
#pragma unroll
    for (int i = threadIdx.y; i < 32; i += 8)
        out[(size_t)(bx + i) * R + by + x] = t[x][i];
}

__global__ void cat_bias_kernel(const float* a, const float* b, const float* c,
                                float* out, int n)
{
    int i = blockIdx.x * 256 + threadIdx.x;
    if (i < n) out[i] = a[i];
    else if (i < 2 * n) out[i] = b[i - n];
    else if (i < 3 * n) out[i] = c[i - 2 * n];
}

__global__ __launch_bounds__(256)
void rowsum_reduce_kernel(const float* __restrict__ rsp, float* __restrict__ rs)
{
    int row = blockIdx.x * 256 + threadIdx.x;
    if (row < NTOK) {
        float s = 0.0f;
#pragma unroll
        for (int i = 0; i < NPART; i++) s += rsp[(size_t)row * NPART + i];
        rs[row] = s;
    }
}

// ---------------------------------------------------------------------------
extern "C" void kernel_launch(void* const* d_in, const int* in_sizes, int n_in,
                              void* d_out, int out_size)
{
    const float* x  = (const float*)d_in[0];
    const float* Wq = (const float*)d_in[1];
    const float* Wk = (const float*)d_in[2];
    const float* Wv = (const float*)d_in[3];
    const float* bq = (const float*)d_in[4];
    const float* bk = (const float*)d_in[5];
    const float* bv = (const float*)d_in[6];
    float* out = (float*)d_out;

    __half *Xh, *Wt, *QKV, *Vt, *E;
    float *bcat, *rsp, *rowsum;
    cudaGetSymbolAddress((void**)&Xh,     g_Xh);
    cudaGetSymbolAddress((void**)&Wt,     g_Wt);
    cudaGetSymbolAddress((void**)&bcat,   g_bcat);
    cudaGetSymbolAddress((void**)&QKV,    g_QKV);
    cudaGetSymbolAddress((void**)&Vt,     g_Vt);
    cudaGetSymbolAddress((void**)&E,      g_E);
    cudaGetSymbolAddress((void**)&rsp,    g_rsp);
    cudaGetSymbolAddress((void**)&rowsum, g_rowsum);

    const int M = NTOK, D = DMODEL;

    cudaFuncSetAttribute(hgemm_nt<0>, cudaFuncAttributeMaxDynamicSharedMemorySize, GEMM_SMEM);
    cudaFuncSetAttribute(hgemm_nt<1>, cudaFuncAttributeMaxDynamicSharedMemorySize, GEMM_SMEM);
    cudaFuncSetAttribute(hgemm_nt<2>, cudaFuncAttributeMaxDynamicSharedMemorySize, GEMM_SMEM);

    // 1. inputs -> half (W transposed+concatenated), bias concat
    cvt_f2h_kernel<<<512, 256>>>(x, Xh, M * D / 4);
    {
        dim3 g(D / 32, D / 32), t(32, 8);
        transpose_f2h_kernel<<<g, t>>>(Wq, Wt + 0 * D * D, D, D);
        transpose_f2h_kernel<<<g, t>>>(Wk, Wt + 1 * D * D, D, D);
        transpose_f2h_kernel<<<g, t>>>(Wv, Wt + 2 * D * D, D, D);
    }
    cat_bias_kernel<<<(D3 + 255) / 256, 256>>>(bq, bk, bv, bcat, D);

    // 2. fused QKV projection (persistent): 24x32 tiles
    hgemm_nt<0><<<PGRID, 128, GEMM_SMEM>>>(Xh, D, Wt, D, bcat, nullptr,
                                           QKV, D3, M / BM, D3 / BN, D, D3, 1.0f);

    // 3. V^T
    {
        dim3 g(D / 32, M / 32), t(32, 8);
        transpose_h2h_kernel<<<g, t>>>(QKV + 2 * D, D3, Vt, M, D);
    }

    // 4. E = exp(Q K^T / 32), partial rowsums (persistent): 32x32 tiles
    hgemm_nt<1><<<PGRID, 128, GEMM_SMEM>>>(QKV + 0 * D, D3, QKV + 1 * D, D3,
                                           nullptr, rsp, E, M,
                                           M / BM, M / BN, D, M, 1.0f / 32.0f);

    // 5. reduce partials
    rowsum_reduce_kernel<<<(M + 255) / 256, 256>>>(rsp, rowsum);

    // 6. out = (E @ Vt^T) / rowsum (persistent): 32x8 tiles
    hgemm_nt<2><<<PGRID, 128, GEMM_SMEM>>>(E, M, Vt, M, rowsum, nullptr,
                                           out, D, M / BM, D / BN, M, D, 1.0f);
}